// round 13
// baseline (speedup 1.0000x reference)
#include <cuda_runtime.h>
#include <cstdint>

#define NN   256
#define BB   8
#define SS   14
#define BS   (BB*SS)
#define NDAT 12   // S - len(PILOTS)

#define THREADS       512
#define STAGES        6
#define CHUNK_ROWS    16
#define CHUNK_BYTES   (CHUNK_ROWS * NN * 4)      // 16384 (one array's rows)
#define STAGE_BYTES   (2 * CHUNK_BYTES)          // 32768 (cr + ci)
#define NCHUNK        16                         // 256 rows / 16

// dynamic smem layout
#define OFF_STAGE  0
#define OFF_HS     (STAGES * STAGE_BYTES)        // 196608
#define OFF_XS     (OFF_HS + 2048)
#define OFF_AA     (OFF_XS + 2176)
#define OFF_W16    (OFF_AA + 2176)
#define OFF_MBAR   (OFF_W16 + 128)
#define SMEM_TOTAL (OFF_MBAR + STAGES * 8)       // 203184

#define WAIT_MBAR(mb, ph)                                                     \
    asm volatile("{\n\t.reg .pred P;\n\t"                                     \
                 "WL_%=:\n\t"                                                 \
                 "mbarrier.try_wait.parity.acquire.cta.shared::cta.b64 P, [%0], %1, 0x989680;\n\t" \
                 "@P bra WD_%=;\n\t"                                          \
                 "bra WL_%=;\n\t"                                             \
                 "WD_%=:\n\t}"                                                \
                 :: "r"(mb), "r"(ph) : "memory")

// TMA bulk copy with L2 evict_last hint: cov should persist in L2 across
// graph replays (42 MB unique footprint < 126 MB L2).
__device__ __forceinline__ void tma_chunk(uint32_t dst, const float* src,
                                          uint32_t mb, uint64_t pol)
{
    asm volatile("cp.async.bulk.shared::cluster.global.mbarrier::complete_tx::bytes"
                 ".L2::cache_hint [%0], [%1], %2, [%3], %4;"
                 :: "r"(dst), "l"(src), "r"((uint32_t)CHUNK_BYTES), "r"(mb),
                    "l"(pol)
                 : "memory");
}

// ---------------------------------------------------------------------------
// Balanced persistent-stream kernel (R12) + L2 evict_last on cov stream.
// Grid = 112 blocks (one per (b,s)) x 512 threads; 1 block/SM, even work.
// Block streams its 512 KB cov slice as 16 chunks of 16 rows through a
// 6-stage x 32 KB smem ring (cp.async.bulk), 1 row per warp per chunk.
// ---------------------------------------------------------------------------
__global__ void __launch_bounds__(THREADS, 1)
fused_kernel(const float* __restrict__ xr,
             const float* __restrict__ xi,
             const float* __restrict__ cr,
             const float* __restrict__ ci,
             const float* __restrict__ zr,
             const float* __restrict__ zi,
             const int*   __restrict__ shift,
             const int*   __restrict__ gidx,
             float*       __restrict__ out)
{
    extern __shared__ __align__(16) char smem[];
    uint32_t sb;
    asm("{ .reg .u64 t; cvta.to.shared.u64 t, %1; cvt.u32.u64 %0, t; }"
        : "=r"(sb) : "l"(smem));

    float2* hs  = (float2*)(smem + OFF_HS);
    float2* xs  = (float2*)(smem + OFF_XS);   // [16][17] padded
    float2* aa  = (float2*)(smem + OFF_AA);   // [17][16] padded
    float2* w16 = (float2*)(smem + OFF_W16);

    const int bs   = blockIdx.x;
    const int b    = bs / SS;
    const int s    = bs % SS;
    const int tid  = threadIdx.x;
    const int w    = tid >> 5;
    const int lane = tid & 31;

    const int g   = __ldg(&gidx[s]);
    const int idx = (g == 0) ? 0 : __ldg(&shift[b * NDAT + g - 1]);
    const size_t base = (size_t)idx * NN * NN;
    const float* crb = cr + base;
    const float* cib = ci + base;

    uint64_t pol;
    asm("createpolicy.fractional.L2::evict_last.b64 %0, 1.0;" : "=l"(pol));

    // ---- tid 0: init mbarriers, fill all pipeline stages ----
    if (tid == 0) {
#pragma unroll
        for (int st = 0; st < STAGES; st++)
            asm volatile("mbarrier.init.shared.b64 [%0], %1;"
                         :: "r"(sb + OFF_MBAR + st * 8), "r"(1) : "memory");
        asm volatile("fence.proxy.async.shared::cta;" ::: "memory");
#pragma unroll
        for (int c = 0; c < STAGES; c++) {
            const uint32_t mb  = sb + OFF_MBAR + c * 8;
            const uint32_t dst = sb + OFF_STAGE + c * STAGE_BYTES;
            asm volatile("mbarrier.arrive.expect_tx.shared.b64 _, [%0], %1;"
                         :: "r"(mb), "r"((uint32_t)STAGE_BYTES) : "memory");
            tma_chunk(dst,               crb + c * CHUNK_ROWS * NN, mb, pol);
            tma_chunk(dst + CHUNK_BYTES, cib + c * CHUNK_ROWS * NN, mb, pol);
        }
    }

    // ---- phase 1: DFT on threads 0..255 (overlaps pipeline fill) ----
    if (tid < NN) {
        xs[(tid & 15) * 17 + (tid >> 4)] = make_float2(xr[bs * NN + tid],
                                                       xi[bs * NN + tid]);
        if (tid < 16) {
            float sn, cs;
            sincospif(-(float)tid * 0.125f, &sn, &cs);   // e^{-2pi i t/16}
            w16[tid] = make_float2(cs, sn);
        }
    }
    __syncthreads();

    if (tid < NN) {   // stage A
        const int k0 = tid >> 4, n0 = tid & 15;
        float ar = 0.0f, ai = 0.0f;
#pragma unroll
        for (int n1 = 0; n1 < 16; n1++) {
            const float2 v  = xs[n0 * 17 + n1];
            const float2 ww = w16[(k0 * n1) & 15];
            ar = fmaf(v.x, ww.x, fmaf(-v.y, ww.y, ar));
            ai = fmaf(v.x, ww.y, fmaf( v.y, ww.x, ai));
        }
        float sn, cs;
        sincospif(-(float)(k0 * n0) * (1.0f / 128.0f), &sn, &cs);
        aa[n0 * 17 + k0] = make_float2(ar * cs - ai * sn, ar * sn + ai * cs);
    }
    __syncthreads();

    if (tid < NN) {   // stage B + conj(zc)
        const int k0 = tid & 15, k1 = tid >> 4;
        float Xr = 0.0f, Xi = 0.0f;
#pragma unroll
        for (int n0 = 0; n0 < 16; n0++) {
            const float2 v  = aa[n0 * 17 + k0];
            const float2 ww = w16[(k1 * n0) & 15];
            Xr = fmaf(v.x, ww.x, fmaf(-v.y, ww.y, Xr));
            Xi = fmaf(v.x, ww.y, fmaf( v.y, ww.x, Xi));
        }
        const float a  = zr[tid];
        const float bq = -zi[tid];
        hs[tid] = make_float2(Xr * a - Xi * bq, Xr * bq + Xi * a);
    }
    __syncthreads();

    // h registers matching the conflict-free smem read pattern:
    //   f4[lane]    -> m = 4*lane .. 4*lane+3
    //   f4[32+lane] -> m = 128+4*lane .. 128+4*lane+3
    float2 h[8];
#pragma unroll
    for (int j = 0; j < 4; j++) {
        h[j]     = hs[lane * 4 + j];
        h[4 + j] = hs[128 + lane * 4 + j];
    }

    // ---- phase 2: consume 16 chunks through the 6-stage ring ----
    int st = 0, ph = 0;
    for (int c = 0; c < NCHUNK; c++) {
        const uint32_t mb = sb + OFF_MBAR + st * 8;

        WAIT_MBAR(mb, (uint32_t)ph);

        const float4* crs = (const float4*)(smem + OFF_STAGE + st * STAGE_BYTES)
                            + w * 64;                    // this warp's cr row
        const float4* cis = crs + (CHUNK_BYTES / 16);    // matching ci row

        const float4 a0 = crs[lane];
        const float4 a1 = crs[32 + lane];
        const float4 c0 = cis[lane];
        const float4 c1 = cis[32 + lane];

        float re = 0.0f;
        re = fmaf(a0.x, h[0].x, fmaf(-c0.x, h[0].y, re));
        re = fmaf(a0.y, h[1].x, fmaf(-c0.y, h[1].y, re));
        re = fmaf(a0.z, h[2].x, fmaf(-c0.z, h[2].y, re));
        re = fmaf(a0.w, h[3].x, fmaf(-c0.w, h[3].y, re));
        re = fmaf(a1.x, h[4].x, fmaf(-c1.x, h[4].y, re));
        re = fmaf(a1.y, h[5].x, fmaf(-c1.y, h[5].y, re));
        re = fmaf(a1.z, h[6].x, fmaf(-c1.z, h[6].y, re));
        re = fmaf(a1.w, h[7].x, fmaf(-c1.w, h[7].y, re));

#pragma unroll
        for (int o = 16; o > 0; o >>= 1)
            re += __shfl_xor_sync(0xffffffffu, re, o);

        if (lane == 0)
            out[bs * NN + c * CHUNK_ROWS + w] = re;

        __syncthreads();   // all warps done with this stage

        if (tid == 0 && c + STAGES < NCHUNK) {   // re-arm with chunk c+STAGES
            const int cn = c + STAGES;
            const uint32_t dst = sb + OFF_STAGE + st * STAGE_BYTES;
            asm volatile("mbarrier.arrive.expect_tx.shared.b64 _, [%0], %1;"
                         :: "r"(mb), "r"((uint32_t)STAGE_BYTES) : "memory");
            tma_chunk(dst,               crb + cn * CHUNK_ROWS * NN, mb, pol);
            tma_chunk(dst + CHUNK_BYTES, cib + cn * CHUNK_ROWS * NN, mb, pol);
        }

        if (++st == STAGES) { st = 0; ph ^= 1; }
    }
}

extern "C" void kernel_launch(void* const* d_in, const int* in_sizes, int n_in,
                              void* d_out, int out_size)
{
    const float* xr    = (const float*)d_in[0];
    const float* xi    = (const float*)d_in[1];
    const float* cr    = (const float*)d_in[2];
    const float* ci    = (const float*)d_in[3];
    const float* zr    = (const float*)d_in[4];
    const float* zi    = (const float*)d_in[5];
    const int*   shift = (const int*)d_in[6];
    const int*   gidx  = (const int*)d_in[7];

    cudaFuncSetAttribute(fused_kernel,
                         cudaFuncAttributeMaxDynamicSharedMemorySize,
                         SMEM_TOTAL);

    fused_kernel<<<BS, THREADS, SMEM_TOTAL>>>(xr, xi, cr, ci, zr, zi,
                                              shift, gidx, (float*)d_out);
}